// round 7
// baseline (speedup 1.0000x reference)
#include <cuda_runtime.h>
#include <cuda_fp16.h>
#include <cstdint>

// ---------------- problem constants ----------------
#define SEQ_LEN   16384
#define T_OUT     16376
#define C_IN      64
#define N_F       64
#define K_W       9
#define N_BATCH   32

#define TILE_M    256
#define TILES_PB  (SEQ_LEN / TILE_M)       // 64
#define N_TILES   (N_BATCH * TILES_PB)     // 2048
#define GRID_CTAS 296                      // 148 SMs * 2 persistent CTAs

// ---------------- SMEM layout ----------------
// Weights: 64 filter rows, each 576 fp16 (9 taps x 64 ch), padded row stride
// 1168 B (= 73 x 16B chunks, 73 % 8 == 1 -> conflict-free ldmatrix across rows).
#define WSTRIDE    1168
#define SMEM_W     0
#define SMEM_BIAS  (64 * WSTRIDE)                // 74752 (16B aligned)
#define SMEM_X     (SMEM_BIAS + 256)             // 75008 (128B aligned)
#define X_ROWS     (TILE_M + 8)                  // 264 rows staged (tap halo)
#define SMEM_TOTAL (SMEM_X + X_ROWS * 128)       // 108800 B -> 2 CTAs/SM

__device__ __forceinline__ uint32_t smem_to_u32(const void* smem_ptr) {
    uint32_t addr;
    asm("{ .reg .u64 tmp; cvta.to.shared.u64 tmp, %1; cvt.u32.u64 %0, tmp; }"
        : "=r"(addr) : "l"(smem_ptr));
    return addr;
}

// ldmatrix x4: 4 8x8 b16 matrices; every lane supplies one row address.
#define LDSM_X4(r0, r1, r2, r3, addr) \
    asm volatile("ldmatrix.sync.aligned.m8n8.x4.shared.b16 {%0,%1,%2,%3}, [%4];" \
        : "=r"(r0), "=r"(r1), "=r"(r2), "=r"(r3) : "r"(addr))

#define MMA_16816(acc, a0, a1, a2, a3, b0, b1) \
    asm volatile( \
        "mma.sync.aligned.m16n8k16.row.col.f32.f16.f16.f32 " \
        "{%0,%1,%2,%3}, {%4,%5,%6,%7}, {%8,%9}, {%0,%1,%2,%3};" \
        : "+f"((acc)[0]), "+f"((acc)[1]), "+f"((acc)[2]), "+f"((acc)[3]) \
        : "r"(a0), "r"(a1), "r"(a2), "r"(a3), "r"(b0), "r"(b1))

// ---------------- kernel ----------------
// 128 threads = 4 warps. Warp w owns output rows [w*64, w*64+64) of the tile
// and ALL 64 filters: accum = 4 m-tiles x 8 n-tiles x 4 f32 = 128 regs.
// Per k-step (tap,kc): load 8 B fragments once (4 ldmatrix.x4), then loop
// 4 m-tiles { 1 A ldmatrix.x4 + 8 mma } -> B smem traffic amortized over 64 rows.
__global__ void __launch_bounds__(128)
conv1d_hmma_kernel(const float* __restrict__ x,
                   const float* __restrict__ w,
                   const float* __restrict__ bias,
                   float* __restrict__ out)
{
    extern __shared__ __align__(16) char smem[];
    const uint32_t smem_u = smem_to_u32(smem);
    const int tid  = threadIdx.x;
    const int lane = tid & 31;
    const int warp = tid >> 5;

    // ---- one-time: weights fp32 -> fp16 into padded SMEM rows ----
    // chunk = 8 fp16 = 16B; 72 chunks per filter row; 64*72 = 4608 chunks.
    for (int idx = tid; idx < 64 * 72; idx += 128) {
        const int f = idx / 72;
        const int j = idx - f * 72;
        const float4* s = (const float4*)(w + (size_t)f * 576 + (size_t)j * 8);
        float4 v0 = s[0];
        float4 v1 = s[1];
        __half2 h0 = __floats2half2_rn(v0.x, v0.y);
        __half2 h1 = __floats2half2_rn(v0.z, v0.w);
        __half2 h2 = __floats2half2_rn(v1.x, v1.y);
        __half2 h3 = __floats2half2_rn(v1.z, v1.w);
        uint4 pk;
        pk.x = *(uint32_t*)&h0; pk.y = *(uint32_t*)&h1;
        pk.z = *(uint32_t*)&h2; pk.w = *(uint32_t*)&h3;
        *(uint4*)(smem + SMEM_W + f * WSTRIDE + j * 16) = pk;
    }
    if (tid < N_F) ((float*)(smem + SMEM_BIAS))[tid] = bias[tid];
    // visibility of w/bias ensured by the __syncthreads inside the tile loop

    // ---- per-lane ldmatrix base addresses ----
    // B (weights): x4 covers an n-tile PAIR: lanes 0-15 -> nt even (k-half via
    // bit3), lanes 16-31 -> nt odd. n-row = pair*16 + (lane>>4)*8 + (lane&7).
    const uint32_t b_lanebase = smem_u + SMEM_W
        + (uint32_t)((((lane >> 4) * 8 + (lane & 7)) * WSTRIDE) + ((lane >> 3) & 1) * 16);
    // A (x): lanes 0-15 -> rows 0-15 col-half 0, lanes 16-31 -> col-half 1.
    const int arow0 = warp * 64 + (lane & 15);
    const int ahalf = lane >> 4;

    for (int tile = blockIdx.x; tile < N_TILES; tile += GRID_CTAS) {
        const int batch = tile >> 6;                 // tile / TILES_PB
        const int tb    = (tile & (TILES_PB - 1)) << 8;
        const float* xb = x + (size_t)batch * (SEQ_LEN * C_IN);

        __syncthreads();  // previous tile's smem reads done (and w staged, iter 0)

        // ---- stage x rows [tb, tb+263] as fp16, XOR-128 swizzled ----
        for (int ci = tid; ci < X_ROWS * 8; ci += 128) {
            const int r  = ci >> 3;
            const int c8 = ci & 7;
            int rg = tb + r;
            if (rg > SEQ_LEN - 1) rg = SEQ_LEN - 1;  // halo clamp: feeds discarded t only
            const float4* s = (const float4*)(xb + (size_t)rg * 64 + c8 * 8);
            float4 v0 = s[0];
            float4 v1 = s[1];
            __half2 h0 = __floats2half2_rn(v0.x, v0.y);
            __half2 h1 = __floats2half2_rn(v0.z, v0.w);
            __half2 h2 = __floats2half2_rn(v1.x, v1.y);
            __half2 h3 = __floats2half2_rn(v1.z, v1.w);
            uint4 pk;
            pk.x = *(uint32_t*)&h0; pk.y = *(uint32_t*)&h1;
            pk.z = *(uint32_t*)&h2; pk.w = *(uint32_t*)&h3;
            const int sc = c8 ^ (r & 7);
            *(uint4*)(smem + SMEM_X + r * 128 + sc * 16) = pk;
        }
        __syncthreads();

        // ---- mainloop ----
        float acc[4][8][4];
        #pragma unroll
        for (int mt = 0; mt < 4; mt++)
            #pragma unroll
            for (int nt = 0; nt < 8; nt++)
                #pragma unroll
                for (int i = 0; i < 4; i++)
                    acc[mt][nt][i] = 0.0f;

        for (int tap = 0; tap < K_W; tap++) {
            #pragma unroll
            for (int kc = 0; kc < 4; kc++) {
                // B fragments: all 8 n-tiles for this (tap, kc)
                uint32_t bfr[8][2];
                const uint32_t bko = (uint32_t)((tap * 64 + kc * 16) * 2);
                #pragma unroll
                for (int p = 0; p < 4; p++) {
                    LDSM_X4(bfr[2 * p][0], bfr[2 * p][1],
                            bfr[2 * p + 1][0], bfr[2 * p + 1][1],
                            b_lanebase + (uint32_t)(p * 16 * WSTRIDE) + bko);
                }
                // A fragment per m-tile, then 8 mma against held B frags
                #pragma unroll
                for (int mt = 0; mt < 4; mt++) {
                    const int row = arow0 + mt * 16 + tap;
                    const uint32_t chunk = (uint32_t)((kc * 2 + ahalf) ^ (row & 7));
                    const uint32_t aaddr = smem_u + SMEM_X
                        + (uint32_t)(row * 128) + chunk * 16;
                    uint32_t a0, a1, a2, a3;
                    LDSM_X4(a0, a1, a2, a3, aaddr);
                    #pragma unroll
                    for (int nt = 0; nt < 8; nt++) {
                        MMA_16816(acc[mt][nt], a0, a1, a2, a3,
                                  bfr[nt][0], bfr[nt][1]);
                    }
                }
            }
        }

        // ---- epilogue: add bias, store fp32 ----
        // C fragment: regs {0,1} -> row lane/4, cols 2*(lane%4)+{0,1};
        //             regs {2,3} -> row lane/4 + 8.
        const int trow0   = tb + warp * 64 + (lane >> 2);
        const int colbase = (lane & 3) * 2;
        const float* bsm  = (const float*)(smem + SMEM_BIAS);
        #pragma unroll
        for (int mt = 0; mt < 4; mt++) {
            #pragma unroll
            for (int h = 0; h < 2; h++) {
                const int t = trow0 + mt * 16 + h * 8;
                if (t < T_OUT) {
                    float* op = out + ((size_t)batch * T_OUT + t) * N_F;
                    #pragma unroll
                    for (int nt = 0; nt < 8; nt++) {
                        const int col = nt * 8 + colbase;
                        const float2 bv = *(const float2*)(bsm + col);
                        float2 r2;
                        r2.x = acc[mt][nt][h * 2 + 0] + bv.x;
                        r2.y = acc[mt][nt][h * 2 + 1] + bv.y;
                        *(float2*)(op + col) = r2;
                    }
                }
            }
        }
    }
}

// ---------------- launch ----------------
extern "C" void kernel_launch(void* const* d_in, const int* in_sizes, int n_in,
                              void* d_out, int out_size)
{
    const float* x    = (const float*)d_in[0];
    const float* w    = (const float*)d_in[1];
    const float* bias = (const float*)d_in[2];
    float* out        = (float*)d_out;

    cudaFuncSetAttribute(conv1d_hmma_kernel,
                         cudaFuncAttributeMaxDynamicSharedMemorySize, SMEM_TOTAL);
    conv1d_hmma_kernel<<<GRID_CTAS, 128, SMEM_TOTAL>>>(x, w, bias, out);
}